// round 12
// baseline (speedup 1.0000x reference)
#include <cuda_runtime.h>
#include <cuda_bf16.h>
#include <cuda_fp16.h>
#include <cstdint>

#define N_NODES 8192
#define IN_F    128
#define HID     64
#define OUT_F   128
#define BM      64
#define BN      64

// persistent schedule: 16384 units = 128 mtiles x 128 jblocks, 444 CTAs (=3x148)
// start(c) = 36c + min(c,400)  (CTAs 0..399 have 37 units, rest 36)
#define N_CTAS  444
#define UNIT_Q  36
#define UNIT_R  400
#define CF_THRESH 14800   // start(400)
#define SLOTS   5

// K/V row stride in flash smem: 64 elems + 8 pad = 72 x 2B = 36 words = 9 uint4.
#define KSTRW 36
#define KSTR4 9
// uint4 per buffer: Kh 576, Kl 576, V 1152 -> 2304 u4 = 36864 B ; 2 buffers
#define BUF_U4 2304
#define FLASH_SMEM (2 * BUF_U4 * 16)   // 73728 B -> 3 CTAs/SM fit 221184 B

// gemm_prep smem B row stride: 128 bf16 = 64 words data + 4 pad = 68 words = 17 u4
#define PSTRW 68
#define PSTR4 17
#define PREP_SMEM (2 * 128 * PSTRW * 4)   // Bh + Bl = 69632 B

// ---------------- scratch (static device globals; no allocs allowed) -----
__device__ __align__(16) __nv_bfloat16 g_hh[N_NODES * IN_F];   // h hi
__device__ __align__(16) __nv_bfloat16 g_hl[N_NODES * IN_F];   // h lo
__device__ __align__(16) __nv_bfloat16 g_Wth[256 * IN_F];      // Wcat^T hi [col][k]
__device__ __align__(16) __nv_bfloat16 g_Wtl[256 * IN_F];      // Wcat^T lo
__device__ __align__(16) __nv_bfloat16 g_Qh[N_NODES * HID];
__device__ __align__(16) __nv_bfloat16 g_Ql[N_NODES * HID];
__device__ __align__(16) __nv_bfloat16 g_Kh[N_NODES * HID];
__device__ __align__(16) __nv_bfloat16 g_Kl[N_NODES * HID];
__device__ __align__(16) __half g_Vt[OUT_F * N_NODES];         // V^T fp16 [feat][j]
// partial slots per m-tile + completion counters
__device__ __align__(16) float g_Op[SLOTS][N_NODES][OUT_F];
__device__ float g_pm[SLOTS][N_NODES];
__device__ float g_pl[SLOTS][N_NODES];
__device__ int   g_cnt[128];

// ---------------- helpers --------------------------------------------------
__device__ __forceinline__ void cp16(void* s, const void* g) {
    unsigned sa = (unsigned)__cvta_generic_to_shared(s);
    asm volatile("cp.async.cg.shared.global [%0], [%1], 16;\n" :: "r"(sa), "l"(g));
}
__device__ __forceinline__ void cp_commit() { asm volatile("cp.async.commit_group;\n"); }
template <int N> __device__ __forceinline__ void cp_wait() {
    asm volatile("cp.async.wait_group %0;\n" :: "n"(N));
}
__device__ __forceinline__ void mma_bf16(float c[4],
                                         unsigned a0, unsigned a1, unsigned a2, unsigned a3,
                                         unsigned b0, unsigned b1) {
    asm volatile(
        "mma.sync.aligned.m16n8k16.row.col.f32.bf16.bf16.f32 "
        "{%0,%1,%2,%3}, {%4,%5,%6,%7}, {%8,%9}, {%0,%1,%2,%3};\n"
        : "+f"(c[0]), "+f"(c[1]), "+f"(c[2]), "+f"(c[3])
        : "r"(a0), "r"(a1), "r"(a2), "r"(a3), "r"(b0), "r"(b1));
}
__device__ __forceinline__ void mma_f16(float c[4],
                                        unsigned a0, unsigned a1, unsigned a2, unsigned a3,
                                        unsigned b0, unsigned b1) {
    asm volatile(
        "mma.sync.aligned.m16n8k16.row.col.f32.f16.f16.f32 "
        "{%0,%1,%2,%3}, {%4,%5,%6,%7}, {%8,%9}, {%0,%1,%2,%3};\n"
        : "+f"(c[0]), "+f"(c[1]), "+f"(c[2]), "+f"(c[3])
        : "r"(a0), "r"(a1), "r"(a2), "r"(a3), "r"(b0), "r"(b1));
}
__device__ __forceinline__ unsigned pack_bf2(__nv_bfloat16 a, __nv_bfloat16 b) {
    return (unsigned)__bfloat16_as_ushort(a) |
           ((unsigned)__bfloat16_as_ushort(b) << 16);
}
__device__ __forceinline__ unsigned pack_h2(__half a, __half b) {
    return (unsigned)__half_as_ushort(a) |
           ((unsigned)__half_as_ushort(b) << 16);
}
__device__ __forceinline__ void split_bf(float v, __nv_bfloat16& hi, __nv_bfloat16& lo) {
    hi = __float2bfloat16(v);
    lo = __float2bfloat16(v - __bfloat162float(hi));
}
__device__ __forceinline__ int cfirst_of(int ut) {
    return (ut < CF_THRESH) ? (ut / 37) : ((ut - UNIT_R) / UNIT_Q);
}

// ---------------- split: h and Wcat^T -> bf16 hi/lo + counter reset --------
__global__ __launch_bounds__(256)
void split_kernel(const float* __restrict__ h,
                  const float* __restrict__ Ws,
                  const float* __restrict__ Wt,
                  const float* __restrict__ Wc) {
    const int bid = blockIdx.x;
    if (bid < 1024) {
        int idx = (bid * 256 + threadIdx.x) * 4;
        float4 v = *(const float4*)(h + idx);
        union { __nv_bfloat16 b[4]; uint2 u; } ph, pl;
        split_bf(v.x, ph.b[0], pl.b[0]);
        split_bf(v.y, ph.b[1], pl.b[1]);
        split_bf(v.z, ph.b[2], pl.b[2]);
        split_bf(v.w, ph.b[3], pl.b[3]);
        *(uint2*)(g_hh + idx) = ph.u;
        *(uint2*)(g_hl + idx) = pl.u;
    } else {
        if (bid == 1024 && threadIdx.x < 128) g_cnt[threadIdx.x] = 0;
        int t = (bid - 1024) * 256 + threadIdx.x;   // 0..8191
        int c  = t >> 5;                            // concat col 0..255
        int k0 = (t & 31) * 4;
        const float* W; int stride, cc;
        if (c < 64)       { W = Ws; stride = 64;  cc = c; }
        else if (c < 128) { W = Wt; stride = 64;  cc = c - 64; }
        else              { W = Wc; stride = 128; cc = c - 128; }
        union { __nv_bfloat16 b[4]; uint2 u; } ph, pl;
#pragma unroll
        for (int j = 0; j < 4; j++)
            split_bf(W[(k0 + j) * stride + cc], ph.b[j], pl.b[j]);
        *(uint2*)(g_Wth + c * IN_F + k0) = ph.u;
        *(uint2*)(g_Wtl + c * IN_F + k0) = pl.u;
    }
}

// ---------------- gemm_prep: C = h @ Wcat (3-term bf16) --------------------
__global__ __launch_bounds__(128, 2)
void gemm_prep() {
    extern __shared__ __align__(16) unsigned char psmem[];
    unsigned* sBh = (unsigned*)psmem;                    // [128][68 words]
    unsigned* sBl = sBh + 128 * PSTRW;

    const int tid  = threadIdx.x;
    const int warp = tid >> 5;
    const int lane = tid & 31;
    const int lr   = lane >> 2;
    const int qi   = lane & 3;

    const int mtile = blockIdx.x & 127;
    const int ntile = blockIdx.x >> 7;
    const int row0  = mtile * 64 + warp * 16 + lr;
    const int row1  = row0 + 8;

    {
        const uint4* gWh4 = (const uint4*)g_Wth;
        const uint4* gWl4 = (const uint4*)g_Wtl;
        uint4* sBh4 = (uint4*)sBh;
        uint4* sBl4 = (uint4*)sBl;
#pragma unroll
        for (int i = tid; i < 2048; i += 128) {
            int r = i >> 4, u = i & 15;
            cp16(&sBh4[r * PSTR4 + u], &gWh4[(ntile * 128 + r) * 16 + u]);
            cp16(&sBl4[r * PSTR4 + u], &gWl4[(ntile * 128 + r) * 16 + u]);
        }
        cp_commit();
    }

    const unsigned* hh32 = (const unsigned*)g_hh;
    const unsigned* hl32 = (const unsigned*)g_hl;
    unsigned ah[8][4], al[8][4];
#pragma unroll
    for (int kt = 0; kt < 8; kt++) {
        int b0 = row0 * 64 + qi + 8 * kt;
        int b1 = row1 * 64 + qi + 8 * kt;
        ah[kt][0] = hh32[b0];     ah[kt][1] = hh32[b1];
        ah[kt][2] = hh32[b0 + 4]; ah[kt][3] = hh32[b1 + 4];
        al[kt][0] = hl32[b0];     al[kt][1] = hl32[b1];
        al[kt][2] = hl32[b0 + 4]; al[kt][3] = hl32[b1 + 4];
    }

    float C[16][4];
#pragma unroll
    for (int nt = 0; nt < 16; nt++)
        C[nt][0] = C[nt][1] = C[nt][2] = C[nt][3] = 0.f;

    cp_wait<0>();
    __syncthreads();

#pragma unroll
    for (int kt = 0; kt < 8; kt++) {
#pragma unroll
        for (int g2 = 0; g2 < 4; g2++) {
            unsigned b0[4], b1[4], c0[4], c1[4];
#pragma unroll
            for (int i = 0; i < 4; i++) {
                int nt = 4 * g2 + i;
                int bi = (8 * nt + lr) * PSTRW + qi + 8 * kt;
                b0[i] = sBh[bi]; b1[i] = sBh[bi + 4];
                c0[i] = sBl[bi]; c1[i] = sBl[bi + 4];
            }
#pragma unroll
            for (int i = 0; i < 4; i++)
                mma_bf16(C[4*g2+i], ah[kt][0], ah[kt][1], ah[kt][2], ah[kt][3], b0[i], b1[i]);
#pragma unroll
            for (int i = 0; i < 4; i++)
                mma_bf16(C[4*g2+i], al[kt][0], al[kt][1], al[kt][2], al[kt][3], b0[i], b1[i]);
#pragma unroll
            for (int i = 0; i < 4; i++)
                mma_bf16(C[4*g2+i], ah[kt][0], ah[kt][1], ah[kt][2], ah[kt][3], c0[i], c1[i]);
        }
    }

    if (ntile == 0) {
#pragma unroll
        for (int nt = 0; nt < 16; nt++) {
            __nv_bfloat16 h0, l0, h1, l1, h2, l2, h3, l3;
            split_bf(C[nt][0], h0, l0); split_bf(C[nt][1], h1, l1);
            split_bf(C[nt][2], h2, l2); split_bf(C[nt][3], h3, l3);
            int col = 8 * nt + 2 * qi;
            __nv_bfloat16* dh = (col < 64) ? g_Qh : g_Kh;
            __nv_bfloat16* dl = (col < 64) ? g_Ql : g_Kl;
            int c = col & 63;
            *(unsigned*)&dh[(size_t)row0 * HID + c] = pack_bf2(h0, h1);
            *(unsigned*)&dl[(size_t)row0 * HID + c] = pack_bf2(l0, l1);
            *(unsigned*)&dh[(size_t)row1 * HID + c] = pack_bf2(h2, h3);
            *(unsigned*)&dl[(size_t)row1 * HID + c] = pack_bf2(l2, l3);
        }
    } else {
#pragma unroll
        for (int nt = 0; nt < 16; nt++) {
            int col = 8 * nt + 2 * qi;
            g_Vt[(size_t)col       * N_NODES + row0] = __float2half_rn(C[nt][0]);
            g_Vt[(size_t)(col + 1) * N_NODES + row0] = __float2half_rn(C[nt][1]);
            g_Vt[(size_t)col       * N_NODES + row1] = __float2half_rn(C[nt][2]);
            g_Vt[(size_t)(col + 1) * N_NODES + row1] = __float2half_rn(C[nt][3]);
        }
    }
}

// ---------------- flash attention (persistent, occ 3, fused merge) ---------
__global__ __launch_bounds__(128, 3)
void flash_kernel(const int* __restrict__ adj, float* __restrict__ out) {
    extern __shared__ __align__(16) unsigned char dynsmem[];
    uint4* base4 = (uint4*)dynsmem;
    __shared__ int s_flag;

    const int tid  = threadIdx.x;
    const int warp = tid >> 5;
    const int lane = tid & 31;
    const int lr   = lane >> 2;
    const int qi   = lane & 3;

    const int c  = blockIdx.x;
    const int u0 = UNIT_Q * c + min(c, UNIT_R);
    const int u1 = u0 + UNIT_Q + (c < UNIT_R ? 1 : 0);

    const int2*  adj2 = (const int2*)adj;
    const uint4* gKh4 = (const uint4*)g_Kh;
    const uint4* gKl4 = (const uint4*)g_Kl;
    const uint4* gV4  = (const uint4*)g_Vt;
    const unsigned* qh32 = (const unsigned*)g_Qh;
    const unsigned* ql32 = (const unsigned*)g_Ql;

    int u = u0;
    while (u < u1) {
        const int t    = u >> 7;           // m-tile
        const int jb0  = u & 127;          // first j-block in this tile
        const int nit  = min(128 - jb0, u1 - u);
        const int cf   = cfirst_of(t << 7);
        const int slot = c - cf;
        const int jbase = jb0 * BN;

        const int mr   = t * BM + warp * 16;
        const int row0 = mr + lr;
        const int row1 = row0 + 8;

        // Q fragments (hi/lo)
        unsigned qh[4][4], ql[4][4];
#pragma unroll
        for (int kt = 0; kt < 4; kt++) {
            int b0 = row0 * 32 + qi + 8 * kt;
            int b1 = row1 * 32 + qi + 8 * kt;
            qh[kt][0] = qh32[b0];     qh[kt][1] = qh32[b1];
            qh[kt][2] = qh32[b0 + 4]; qh[kt][3] = qh32[b1 + 4];
            ql[kt][0] = ql32[b0];     ql[kt][1] = ql32[b1];
            ql[kt][2] = ql32[b0 + 4]; ql[kt][3] = ql32[b1 + 4];
        }

        float O[16][4];
#pragma unroll
        for (int v = 0; v < 16; v++)
#pragma unroll
            for (int i = 0; i < 4; i++) O[v][i] = 0.f;
        float m0 = -1e30f, m1 = -1e30f, l0 = 0.f, l1 = 0.f;

        // segment prologue: prior segment (incl. merge) done before refill
        __syncthreads();
        {
            uint4* bKh = base4;
            uint4* bKl = base4 + 576;
            uint4* bV  = base4 + 1152;
#pragma unroll
            for (int i = tid; i < 512; i += 128) {
                int r = i >> 3, cw = i & 7;
                cp16(&bKh[r * KSTR4 + cw], &gKh4[(jbase + r) * 8 + cw]);
                cp16(&bKl[r * KSTR4 + cw], &gKl4[(jbase + r) * 8 + cw]);
            }
#pragma unroll
            for (int i = tid; i < 1024; i += 128) {
                int cl2 = i >> 3, kw = i & 7;
                cp16(&bV[cl2 * KSTR4 + kw], &gV4[cl2 * 1024 + (jbase >> 3) + kw]);
            }
            cp_commit();
        }

        int b_cur = 0;
        for (int it = 0; it < nit; ++it) {
            const int j0 = jbase + it * BN;

            int2 adjA[8], adjB[8];
#pragma unroll
            for (int nt = 0; nt < 8; nt++) {
                adjA[nt] = __ldcs(&adj2[row0 * 4096 + (j0 >> 1) + 4 * nt + qi]);
                adjB[nt] = __ldcs(&adj2[row1 * 4096 + (j0 >> 1) + 4 * nt + qi]);
            }

            cp_wait<0>();
            __syncthreads();   // single barrier: fill(i+1) targets buffer read in i-1

            if (it + 1 < nit) {
                const int jn = j0 + BN;
                uint4* bKh = base4 + (b_cur ^ 1) * BUF_U4;
                uint4* bKl = bKh + 576;
                uint4* bV  = bKh + 1152;
#pragma unroll
                for (int i = tid; i < 512; i += 128) {
                    int r = i >> 3, cw = i & 7;
                    cp16(&bKh[r * KSTR4 + cw], &gKh4[(jn + r) * 8 + cw]);
                    cp16(&bKl[r * KSTR4 + cw], &gKl4[(jn + r) * 8 + cw]);
                }
#pragma unroll
                for (int i = tid; i < 1024; i += 128) {
                    int cl2 = i >> 3, kw = i & 7;
                    cp16(&bV[cl2 * KSTR4 + kw], &gV4[cl2 * 1024 + (jn >> 3) + kw]);
                }
                cp_commit();
            }

            const unsigned* sKh32 = (const unsigned*)(base4 + b_cur * BUF_U4);
            const unsigned* sKl32 = sKh32 + 576 * 4;
            const unsigned* sV32  = sKh32 + 1152 * 4;

            // S = Q K^T (3-term bf16 split, chains interleaved x4)
            float S[8][4];
#pragma unroll
            for (int nt = 0; nt < 8; nt++)
                S[nt][0] = S[nt][1] = S[nt][2] = S[nt][3] = 0.f;

#pragma unroll
            for (int kt = 0; kt < 4; kt++) {
#pragma unroll
                for (int gr = 0; gr < 2; gr++) {
                    unsigned b0[4], b1[4], c0[4], c1[4];
#pragma unroll
                    for (int i = 0; i < 4; i++) {
                        int nt = 4 * gr + i;
                        int bi = (8 * nt + lr) * KSTRW + qi + 8 * kt;
                        b0[i] = sKh32[bi]; b1[i] = sKh32[bi + 4];
                        c0[i] = sKl32[bi]; c1[i] = sKl32[bi + 4];
                    }
#pragma unroll
                    for (int i = 0; i < 4; i++)
                        mma_bf16(S[4*gr+i], qh[kt][0], qh[kt][1], qh[kt][2], qh[kt][3], b0[i], b1[i]);
#pragma unroll
                    for (int i = 0; i < 4; i++)
                        mma_bf16(S[4*gr+i], ql[kt][0], ql[kt][1], ql[kt][2], ql[kt][3], b0[i], b1[i]);
#pragma unroll
                    for (int i = 0; i < 4; i++)
                        mma_bf16(S[4*gr+i], qh[kt][0], qh[kt][1], qh[kt][2], qh[kt][3], c0[i], c1[i]);
                }
            }

            // mask + row max
            float rmax0 = -1e30f, rmax1 = -1e30f;
#pragma unroll
            for (int nt = 0; nt < 8; nt++) {
                if (adjA[nt].x <= 0) S[nt][0] = -1e30f;
                if (adjA[nt].y <= 0) S[nt][1] = -1e30f;
                if (adjB[nt].x <= 0) S[nt][2] = -1e30f;
                if (adjB[nt].y <= 0) S[nt][3] = -1e30f;
                rmax0 = fmaxf(rmax0, fmaxf(S[nt][0], S[nt][1]));
                rmax1 = fmaxf(rmax1, fmaxf(S[nt][2], S[nt][3]));
            }
            rmax0 = fmaxf(rmax0, __shfl_xor_sync(0xffffffffu, rmax0, 1));
            rmax0 = fmaxf(rmax0, __shfl_xor_sync(0xffffffffu, rmax0, 2));
            rmax1 = fmaxf(rmax1, __shfl_xor_sync(0xffffffffu, rmax1, 1));
            rmax1 = fmaxf(rmax1, __shfl_xor_sync(0xffffffffu, rmax1, 2));

            float mn0 = fmaxf(m0, rmax0), mn1 = fmaxf(m1, rmax1);
            float sc0 = __expf(m0 - mn0), sc1 = __expf(m1 - mn1);
            m0 = mn0; m1 = mn1;

            // exp + pack P (fp16)
            float rs0 = 0.f, rs1 = 0.f;
            unsigned ap[4][4];
#pragma unroll
            for (int kt2 = 0; kt2 < 4; kt2++) {
#pragma unroll
                for (int half = 0; half < 2; half++) {
                    int nt = 2 * kt2 + half;
                    float p0 = (S[nt][0] > -1e29f) ? __expf(S[nt][0] - mn0) : 0.f;
                    float p1 = (S[nt][1] > -1e29f) ? __expf(S[nt][1] - mn0) : 0.f;
                    float p2 = (S[nt][2] > -1e29f) ? __expf(S[nt][2] - mn1) : 0.f;
                    float p3 = (S[nt][3] > -1e29f) ? __expf(S[nt][3] - mn1) : 0.f;
                    rs0 += p0 + p1;
                    rs1 += p2 + p3;
                    ap[kt2][2 * half + 0] = pack_h2(__float2half_rn(p0), __float2half_rn(p1));
                    ap[kt2][2 * half + 1] = pack_h2(__float2half_rn(p2), __float2half_rn(p3));
                }
            }

            rs0 += __shfl_xor_sync(0xffffffffu, rs0, 1);
            rs0 += __shfl_xor_sync(0xffffffffu, rs0, 2);
            rs1 += __shfl_xor_sync(0xffffffffu, rs1, 1);
            rs1 += __shfl_xor_sync(0xffffffffu, rs1, 2);
            l0 = l0 * sc0 + rs0;
            l1 = l1 * sc1 + rs1;

            if (!__all_sync(0xffffffffu, (sc0 == 1.f) & (sc1 == 1.f))) {
#pragma unroll
                for (int v = 0; v < 16; v++) {
                    O[v][0] *= sc0; O[v][1] *= sc0;
                    O[v][2] *= sc1; O[v][3] *= sc1;
                }
            }

            // O += P V (single fp16 term, chains interleaved x4)
#pragma unroll
            for (int kt2 = 0; kt2 < 4; kt2++) {
#pragma unroll
                for (int gr = 0; gr < 4; gr++) {
                    unsigned v0[4], v1[4];
#pragma unroll
                    for (int i = 0; i < 4; i++) {
                        int vn = 4 * gr + i;
                        int bi = (8 * vn + lr) * KSTRW + qi + 8 * kt2;
                        v0[i] = sV32[bi]; v1[i] = sV32[bi + 4];
                    }
#pragma unroll
                    for (int i = 0; i < 4; i++)
                        mma_f16(O[4*gr+i], ap[kt2][0], ap[kt2][1], ap[kt2][2], ap[kt2][3], v0[i], v1[i]);
                }
            }

            b_cur ^= 1;
        }

        // write this segment's partials (unnormalized)
        float* op = &g_Op[slot][0][0];
#pragma unroll
        for (int vn = 0; vn < 16; vn++) {
            int col = 8 * vn + 2 * qi;
            *(float2*)&op[row0 * OUT_F + col] = make_float2(O[vn][0], O[vn][1]);
            *(float2*)&op[row1 * OUT_F + col] = make_float2(O[vn][2], O[vn][3]);
        }
        if (qi == 0) {
            g_pm[slot][row0] = m0; g_pl[slot][row0] = l0;
            g_pm[slot][row1] = m1; g_pl[slot][row1] = l1;
        }

        // ---- fused merge: last CTA of this tile normalizes + writes out --
        const int ns = cfirst_of((t << 7) + 127) - cf + 1;
        __threadfence();                 // release this CTA's partials
        __syncthreads();
        if (tid == 0) {
            int old = atomicAdd(&g_cnt[t], 1);
            s_flag = (old == ns - 1);
        }
        __syncthreads();
        if (s_flag) {
            __threadfence();             // acquire other CTAs' partials
            const int rbase = t * BM;
            for (int i = tid; i < BM * 32; i += 128) {
                int row = rbase + (i >> 5);
                int cc  = (i & 31) * 4;
                float M = g_pm[0][row];
                float L = g_pl[0][row];
                float4 acc = *(const float4*)&g_Op[0][row][cc];
                for (int s = 1; s < ns; s++) {
                    float m = g_pm[s][row], l = g_pl[s][row];
                    float Mn = fmaxf(M, m);
                    float sa = __expf(M - Mn), sb = __expf(m - Mn);
                    float4 b = *(const float4*)&g_Op[s][row][cc];
                    acc.x = acc.x * sa + b.x * sb;
                    acc.y = acc.y * sa + b.y * sb;
                    acc.z = acc.z * sa + b.z * sb;
                    acc.w = acc.w * sa + b.w * sb;
                    L = L * sa + l * sb;
                    M = Mn;
                }
                float inv = 1.f / L;
                *(float4*)&out[row * OUT_F + cc] =
                    make_float4(acc.x * inv, acc.y * inv, acc.z * inv, acc.w * inv);
            }
        }

        u += nit;
    }
}

// ---------------- launch --------------------------------------------------
extern "C" void kernel_launch(void* const* d_in, const int* in_sizes, int n_in,
                              void* d_out, int out_size) {
    const float* h   = (const float*)d_in[0];
    const int*   adj = (const int*)d_in[1];
    const float* Ws  = (const float*)d_in[2];
    const float* Wt  = (const float*)d_in[3];
    const float* Wc  = (const float*)d_in[4];
    float* out = (float*)d_out;

    split_kernel<<<1056, 256>>>(h, Ws, Wt, Wc);

    cudaFuncSetAttribute(gemm_prep,
                         cudaFuncAttributeMaxDynamicSharedMemorySize, PREP_SMEM);
    gemm_prep<<<256, 128, PREP_SMEM>>>();

    cudaFuncSetAttribute(flash_kernel,
                         cudaFuncAttributeMaxDynamicSharedMemorySize, FLASH_SMEM);
    flash_kernel<<<N_CTAS, 128, FLASH_SMEM>>>(adj, out);
}